// round 6
// baseline (speedup 1.0000x reference)
#include <cuda_runtime.h>
#include <math.h>

// Problem constants
#define BATCH 4
#define NOBJ  256
#define HDIM  512
#define CD1   256      // collision detector hidden 1
#define CD2   128      // collision detector hidden 2

// Output layout (float32, concatenated in reference return order)
#define OFF_MASS 0
#define OFF_FRIC 1024
#define OFF_ELAS 2048
#define OFF_DENS 3072
#define OFF_VEL  4096
#define OFF_FRC  7168
#define OFF_COL  10240

// Scratch: A = x @ cd_w1[:512] + b1   (bias folded), B = x @ cd_w1[512:]
__device__ float g_A[BATCH * NOBJ * CD1];   // 1 MB
__device__ float g_B[BATCH * NOBJ * CD1];   // 1 MB

// ---------------------------------------------------------------------------
// Kernel 1: per-row heads. 8 rows per block, 256 threads.
//  - pp hidden (relu(x@pp_w1+b1)) -> only 4 columns of pp_w2 needed
//  - A/B halves of collision layer 1
//  - velocity / force heads
// ---------------------------------------------------------------------------
__global__ void __launch_bounds__(256) heads_kernel(
    const float* __restrict__ x,
    const float* __restrict__ pp_w1, const float* __restrict__ pp_b1,
    const float* __restrict__ pp_w2, const float* __restrict__ pp_b2,
    const float* __restrict__ cd_w1, const float* __restrict__ cd_b1,
    const float* __restrict__ vel_w, const float* __restrict__ vel_b,
    const float* __restrict__ frc_w, const float* __restrict__ frc_b,
    float* __restrict__ out)
{
    __shared__ float sx[8][HDIM];    // 16 KB
    __shared__ float sh1[8][HDIM];   // 16 KB (pp hidden)

    const int tid  = threadIdx.x;
    const int row0 = blockIdx.x * 8;      // flattened (b*256 + n)

    // load 8 rows of x
    for (int idx = tid; idx < 8 * HDIM; idx += 256) {
        sx[idx >> 9][idx & 511] = x[row0 * HDIM + idx];
    }
    __syncthreads();

    // ---- physics-predictor hidden: thread handles columns tid and tid+256
    {
        float a0[8], a1[8];
        #pragma unroll
        for (int r = 0; r < 8; r++) { a0[r] = 0.f; a1[r] = 0.f; }
        #pragma unroll 4
        for (int k = 0; k < HDIM; k++) {
            float w0 = pp_w1[k * 512 + tid];
            float w1 = pp_w1[k * 512 + tid + 256];
            #pragma unroll
            for (int r = 0; r < 8; r++) {
                float xv = sx[r][k];
                a0[r] = fmaf(xv, w0, a0[r]);
                a1[r] = fmaf(xv, w1, a1[r]);
            }
        }
        float b0  = pp_b1[tid];
        float b1v = pp_b1[tid + 256];
        #pragma unroll
        for (int r = 0; r < 8; r++) {
            sh1[r][tid]       = fmaxf(a0[r] + b0,  0.f);
            sh1[r][tid + 256] = fmaxf(a1[r] + b1v, 0.f);
        }
    }

    // ---- A / B halves of collision layer-1 (bias folded into A)
    {
        float aA[8], aB[8];
        #pragma unroll
        for (int r = 0; r < 8; r++) { aA[r] = 0.f; aB[r] = 0.f; }
        #pragma unroll 4
        for (int k = 0; k < HDIM; k++) {
            float wA = cd_w1[k * CD1 + tid];
            float wB = cd_w1[(k + 512) * CD1 + tid];
            #pragma unroll
            for (int r = 0; r < 8; r++) {
                float xv = sx[r][k];
                aA[r] = fmaf(xv, wA, aA[r]);
                aB[r] = fmaf(xv, wB, aB[r]);
            }
        }
        float bb = cd_b1[tid];
        #pragma unroll
        for (int r = 0; r < 8; r++) {
            g_A[(row0 + r) * CD1 + tid] = aA[r] + bb;
            g_B[(row0 + r) * CD1 + tid] = aB[r];
        }
    }
    __syncthreads();   // sh1 fully written before cross-column warp dots

    // ---- small heads via warp dots: warp r handles row row0+r, tasks q=0..9
    const int warp = tid >> 5;
    const int lane = tid & 31;
    const int r    = warp;
    const int row  = row0 + r;

    for (int q = 0; q < 10; q++) {
        float sum = 0.f;
        if (q < 4) {                           // p[:,q] = sh1 @ pp_w2[:,q]
            for (int k = lane; k < HDIM; k += 32)
                sum = fmaf(sh1[r][k], pp_w2[k * 128 + q], sum);
        } else if (q < 7) {                    // velocities
            int c = q - 4;
            for (int k = lane; k < HDIM; k += 32)
                sum = fmaf(sx[r][k], vel_w[k * 3 + c], sum);
        } else {                               // forces
            int c = q - 7;
            for (int k = lane; k < HDIM; k += 32)
                sum = fmaf(sx[r][k], frc_w[k * 3 + c], sum);
        }
        #pragma unroll
        for (int o = 16; o > 0; o >>= 1)
            sum += __shfl_xor_sync(0xffffffffu, sum, o);
        if (lane == 0) {
            if (q < 4) {
                float s = 1.f / (1.f + expf(-(sum + pp_b2[q])));
                if      (q == 0) out[OFF_MASS + row] = s * 100.f;
                else if (q == 1) out[OFF_FRIC + row] = s;
                else if (q == 2) out[OFF_ELAS + row] = s;
                else             out[OFF_DENS + row] = s * 10.f;
            } else if (q < 7) {
                out[OFF_VEL + row * 3 + (q - 4)] = sum + vel_b[q - 4];
            } else {
                out[OFF_FRC + row * 3 + (q - 7)] = sum + frc_b[q - 7];
            }
        }
    }
}

// ---------------------------------------------------------------------------
// Kernel 2: pairwise collisions. One block per 8x8 row-block tile of the
// upper triangle (incl. diagonal tiles), per batch. 2112 blocks, 256 thr.
// h1 = relu(A[i] + B[j]); h2 = relu(h1 @ W2 + b2); s = h2 . w3 + b3.
// Register-tiled GEMM: thread = 8 pairs x 4 cols; K chunked by 32 in SMEM.
// ---------------------------------------------------------------------------
__global__ void __launch_bounds__(256) pair_kernel(
    const float* __restrict__ cd_w2, const float* __restrict__ cd_b2,
    const float* __restrict__ cd_w3, const float* __restrict__ cd_b3,
    float* __restrict__ out)
{
    __shared__ float sA[8][260];                      // padded: avoid bank conflicts
    __shared__ float sB[8][260];
    __shared__ __align__(16) float sh1[32][64];       // [k-chunk][pair]
    __shared__ __align__(16) float sW2[32][128];      // [k-chunk][col]
    __shared__ float sW3[CD2];
    __shared__ float sB2[CD2];

    const int tid = threadIdx.x;

    // decode (batch, upper-tri tile) from blockIdx
    int b = blockIdx.x / 528;
    int t = blockIdx.x % 528;
    int bi = 0, rem = t;
    while (rem >= 32 - bi) { rem -= 32 - bi; bi++; }
    int bj = bi + rem;
    const int i0 = bi * 8, j0 = bj * 8;
    const int rowbase = b * NOBJ;

    // stage A rows (i-side, bias folded) and B rows (j-side)
    for (int idx = tid; idx < 8 * 256; idx += 256) {
        int rr = idx >> 8, k = idx & 255;
        sA[rr][k] = g_A[(rowbase + i0 + rr) * CD1 + k];
        sB[rr][k] = g_B[(rowbase + j0 + rr) * CD1 + k];
    }
    if (tid < CD2) { sW3[tid] = cd_w3[tid]; sB2[tid] = cd_b2[tid]; }
    __syncthreads();

    const int warp = tid >> 5;        // = ti  (pairs p0..p0+7 share i)
    const int lane = tid & 31;
    const int p0   = warp * 8;
    const int c0   = lane * 4;

    float acc[8][4];
    #pragma unroll
    for (int pi = 0; pi < 8; pi++)
        #pragma unroll
        for (int ci = 0; ci < 4; ci++) acc[pi][ci] = 0.f;

    for (int kc = 0; kc < 8; kc++) {
        const int k0 = kc * 32;
        // build h1 chunk: sh1[kk][p] = relu(A[ti][k0+kk] + B[tj][k0+kk])
        #pragma unroll
        for (int v = 0; v < 8; v++) {
            int idx = v * 256 + tid;
            int kk = idx >> 6;
            int p  = idx & 63;
            sh1[kk][p] = fmaxf(sA[p >> 3][k0 + kk] + sB[p & 7][k0 + kk], 0.f);
        }
        // stage W2 chunk (rows k0..k0+31, contiguous 16 KB)
        {
            const float4* src = (const float4*)(cd_w2 + k0 * CD2);
            float4* dst = (float4*)sW2;
            #pragma unroll
            for (int v = 0; v < 4; v++) dst[v * 256 + tid] = src[v * 256 + tid];
        }
        __syncthreads();

        #pragma unroll
        for (int kk = 0; kk < 32; kk++) {
            float4 ha = *(const float4*)&sh1[kk][p0];
            float4 hb = *(const float4*)&sh1[kk][p0 + 4];
            float4 w  = *(const float4*)&sW2[kk][c0];
            float hv[8] = {ha.x, ha.y, ha.z, ha.w, hb.x, hb.y, hb.z, hb.w};
            float wv[4] = {w.x, w.y, w.z, w.w};
            #pragma unroll
            for (int pi = 0; pi < 8; pi++)
                #pragma unroll
                for (int ci = 0; ci < 4; ci++)
                    acc[pi][ci] = fmaf(hv[pi], wv[ci], acc[pi][ci]);
        }
        __syncthreads();
    }

    // epilogue: bias + relu + dot with w3, reduce across the warp's 32 col-threads
    float partial[8];
    #pragma unroll
    for (int pi = 0; pi < 8; pi++) {
        float s = 0.f;
        #pragma unroll
        for (int ci = 0; ci < 4; ci++) {
            float h2 = fmaxf(acc[pi][ci] + sB2[c0 + ci], 0.f);
            s = fmaf(h2, sW3[c0 + ci], s);
        }
        partial[pi] = s;
    }
    float myS = 0.f;
    #pragma unroll
    for (int pi = 0; pi < 8; pi++) {
        float v = partial[pi];
        #pragma unroll
        for (int o = 16; o > 0; o >>= 1)
            v += __shfl_xor_sync(0xffffffffu, v, o);
        if (lane == pi) myS = v;
    }
    if (lane < 8) {
        int i = i0 + warp;
        int j = j0 + lane;
        float* cm = out + OFF_COL + b * (NOBJ * NOBJ);
        if (i < j) {
            float prob = 1.f / (1.f + expf(-(myS + cd_b3[0])));
            cm[i * NOBJ + j] = prob;
            cm[j * NOBJ + i] = prob;
        } else if (i == j) {
            cm[i * NOBJ + i] = 0.f;   // d_out is poisoned; diagonal must be 0
        }
    }
}

// ---------------------------------------------------------------------------
extern "C" void kernel_launch(void* const* d_in, const int* in_sizes, int n_in,
                              void* d_out, int out_size)
{
    (void)in_sizes; (void)n_in; (void)out_size;
    const float* x     = (const float*)d_in[0];
    const float* pp_w1 = (const float*)d_in[1];
    const float* pp_b1 = (const float*)d_in[2];
    const float* pp_w2 = (const float*)d_in[3];
    const float* pp_b2 = (const float*)d_in[4];
    const float* cd_w1 = (const float*)d_in[5];
    const float* cd_b1 = (const float*)d_in[6];
    const float* cd_w2 = (const float*)d_in[7];
    const float* cd_b2 = (const float*)d_in[8];
    const float* cd_w3 = (const float*)d_in[9];
    const float* cd_b3 = (const float*)d_in[10];
    const float* vel_w = (const float*)d_in[11];
    const float* vel_b = (const float*)d_in[12];
    const float* frc_w = (const float*)d_in[13];
    const float* frc_b = (const float*)d_in[14];
    float* out = (float*)d_out;

    heads_kernel<<<128, 256>>>(x, pp_w1, pp_b1, pp_w2, pp_b2,
                               cd_w1, cd_b1, vel_w, vel_b, frc_w, frc_b, out);
    pair_kernel<<<4 * 528, 256>>>(cd_w2, cd_b2, cd_w3, cd_b3, out);
}